// round 16
// baseline (speedup 1.0000x reference)
#include <cuda_runtime.h>
#include <cuda_fp16.h>
#include <math.h>
#include <stdint.h>

#define NB   4
#define NS   896
#define ND   1024
#define NH   16
#define NDH  64
#define NI   4096
#define NOUT 4096
#define NL   2
#define NM   128
#define NT   1024
#define NBT  4096

typedef __half h16;
typedef long long ll;

__device__ float g_x[NBT * ND];
__device__ h16  g_xh[NBT * ND];
__device__ h16  g_qh[NBT * ND];
__device__ h16  g_kh[NBT * ND];     // K for flash; then reused as h16 residual y
__device__ h16  g_vth[NBT * ND];
__device__ h16  g_t0h[NBT * ND];
__device__ h16  g_ih[(size_t)NBT * NI];
#define WPL (4 * ND * ND + ND * NI + NI * ND)
#define WELEMS (NL * WPL + ND * NOUT)
__device__ h16  g_wh[WELEMS];

__device__ __forceinline__ uint32_t smem_u32(const void* p) {
    uint32_t a;
    asm("{ .reg .u64 t; cvta.to.shared.u64 t, %1; cvt.u32.u64 %0, t; }" : "=r"(a) : "l"(p));
    return a;
}
__device__ __forceinline__ float gelu_f(float x) {
    return 0.5f * x * (1.0f + erff(x * 0.7071067811865476f));
}
__device__ __forceinline__ void ldsm4(uint32_t& r0, uint32_t& r1, uint32_t& r2, uint32_t& r3, uint32_t a) {
    asm volatile("ldmatrix.sync.aligned.m8n8.x4.shared.b16 {%0,%1,%2,%3}, [%4];"
                 : "=r"(r0), "=r"(r1), "=r"(r2), "=r"(r3) : "r"(a));
}
__device__ __forceinline__ void mma16816(float* c, const uint32_t* a, const uint32_t* b) {
    asm volatile("mma.sync.aligned.m16n8k16.row.col.f32.f16.f16.f32 "
                 "{%0,%1,%2,%3},{%4,%5,%6,%7},{%8,%9},{%0,%1,%2,%3};"
                 : "+f"(c[0]), "+f"(c[1]), "+f"(c[2]), "+f"(c[3])
                 : "r"(a[0]), "r"(a[1]), "r"(a[2]), "r"(a[3]), "r"(b[0]), "r"(b[1]));
}
__device__ __forceinline__ void cpasync16(uint32_t dst, const void* src) {
    asm volatile("cp.async.cg.shared.global [%0], [%1], 16;" :: "r"(dst), "l"(src));
}
__device__ __forceinline__ void cpcommit() { asm volatile("cp.async.commit_group;" ::: "memory"); }
template<int N> __device__ __forceinline__ void cpwait() {
    asm volatile("cp.async.wait_group %0;" :: "n"(N) : "memory");
}
__device__ __forceinline__ uint32_t swoff(int r, int c16) {
    return (uint32_t)(r * 128 + ((c16 ^ (r & 7)) * 16));
}
__device__ __forceinline__ uint32_t packh(float a, float b) {
    uint32_t r;
    asm("cvt.rn.f16x2.f32 %0, %1, %2;" : "=r"(r) : "f"(b), "f"(a));
    return r;
}

// ---------------- fp16 warp-MMA GEMM (R8 inner loop, 3-stage cp.async pipeline) ----------------
template<int BN, int ACT, int OUTM>
__global__ void __launch_bounds__(256, 2) tgemm(
    const h16* __restrict__ Ah, const h16* __restrict__ Bh,
    const float* __restrict__ bias, float alpha,
    float* __restrict__ Cf, h16* __restrict__ Ch,
    int K, int lda, int ldb, int ldc,
    ll oA, ll iA, ll oB, ll iB, ll oC, ll iC, int h)
{
    constexpr int ABYTES = 128 * 128;
    constexpr int BBYTES = BN * 128;
    constexpr int STAGE  = ABYTES + BBYTES;
    constexpr int WN     = BN / 2;
    constexpr int NT8    = WN / 8;

    extern __shared__ __align__(128) char smem[];
    const uint32_t sb = smem_u32(smem);
    const int tid = threadIdx.x, lane = tid & 31, wid = tid >> 5;
    const int wm = wid >> 1, wn = wid & 1;

    const int z = blockIdx.z;
    const ll aoff = (ll)(z / h) * oA + (ll)(z % h) * iA;
    const ll boff = (ll)(z / h) * oB + (ll)(z % h) * iB;
    const ll coff = (ll)(z / h) * oC + (ll)(z % h) * iC;
    const int bm = blockIdx.y * 128;
    const int bn = blockIdx.x * BN;
    const h16* a0h = Ah + aoff + (ll)bm * lda;
    const h16* b0h = Bh + boff + (ll)bn * ldb;

    float acc[2][NT8][4];
#pragma unroll
    for (int i = 0; i < 2; i++)
#pragma unroll
        for (int j = 0; j < NT8; j++)
#pragma unroll
            for (int t = 0; t < 4; t++) acc[i][j][t] = 0.0f;

    const int nch = K >> 6;
    const int aRow = (lane & 7) | (((lane >> 3) & 1) << 3);
    const int aC   = lane >> 4;
    const int bRow = (lane & 7) | (((lane >> 4) & 1) << 3);
    const int bC   = (lane >> 3) & 1;

    auto issue = [&](int c, int s) {
        const int k0 = c * 64;
        const uint32_t base = sb + s * STAGE;
        constexpr int TOT = (128 + BN) * 8;
#pragma unroll 4
        for (int u = tid; u < TOT; u += 256) {
            const int chunk = u & 7, row = u >> 3;
            const h16* src; uint32_t dbase; int r, ld;
            if (row < 128) { src = a0h; r = row;       dbase = base;          ld = lda; }
            else           { src = b0h; r = row - 128; dbase = base + ABYTES; ld = ldb; }
            cpasync16(dbase + swoff(r, chunk), src + (ll)r * ld + k0 + chunk * 8);
        }
    };

    issue(0, 0); cpcommit();
    if (nch > 1) { issue(1, 1); cpcommit(); }

    int st = 0;
    for (int c = 0; c < nch; c++) {
        const int nxt = c + 2;
        if (nxt < nch) {
            int s2 = st + 2; if (s2 >= 3) s2 -= 3;
            issue(nxt, s2); cpcommit(); cpwait<2>();
        }
        else if (c + 1 < nch) { cpwait<1>(); }
        else                  { cpwait<0>(); }
        __syncthreads();

        const uint32_t tAh = sb + st * STAGE;
        const uint32_t tBh = tAh + ABYTES;

#pragma unroll
        for (int ks = 0; ks < 4; ks++) {
            uint32_t ah[2][4], bh[NT8][2];
#pragma unroll
            for (int mt = 0; mt < 2; mt++) {
                const int r = wm * 32 + mt * 16 + aRow;
                const int c16 = ks * 2 + aC;
                ldsm4(ah[mt][0], ah[mt][1], ah[mt][2], ah[mt][3], tAh + swoff(r, c16));
            }
#pragma unroll
            for (int nt2 = 0; nt2 < NT8 / 2; nt2++) {
                const int r = wn * WN + nt2 * 16 + bRow;
                const int c16 = ks * 2 + bC;
                ldsm4(bh[2*nt2][0], bh[2*nt2][1], bh[2*nt2+1][0], bh[2*nt2+1][1], tBh + swoff(r, c16));
            }
#pragma unroll
            for (int mt = 0; mt < 2; mt++)
#pragma unroll
                for (int nt = 0; nt < NT8; nt++)
                    mma16816(acc[mt][nt], ah[mt], bh[nt]);
        }
        __syncthreads();
        st++; if (st >= 3) st = 0;
    }

    const int gid = lane >> 2, tig2 = (lane & 3) * 2;

#pragma unroll
    for (int mt = 0; mt < 2; mt++) {
#pragma unroll
        for (int nt = 0; nt < NT8; nt++) {
            const int n = bn + wn * WN + nt * 8 + tig2;
            float bv0 = 0.f, bv1 = 0.f;
            if (bias) { bv0 = bias[n]; bv1 = bias[n + 1]; }
#pragma unroll
            for (int hf = 0; hf < 2; hf++) {
                const int m = bm + wm * 32 + mt * 16 + gid + hf * 8;
                float v0 = acc[mt][nt][hf * 2]     * alpha + bv0;
                float v1 = acc[mt][nt][hf * 2 + 1] * alpha + bv1;
                if (ACT) { v0 = gelu_f(v0); v1 = gelu_f(v1); }
                if (OUTM == 0) {
                    *reinterpret_cast<float2*>(Cf + coff + (ll)m * ldc + n) = make_float2(v0, v1);
                } else {
                    *reinterpret_cast<uint32_t*>(Ch + coff + (ll)m * ldc + n) = packh(v0, v1);
                }
            }
        }
    }
}

#define QSCL 0.18033688011112042f   // 0.125 * log2(e), folded into Q projection

// ---------------- fused QKV projection: grid (8, 32, 3), 3-stage ----------------
__global__ void __launch_bounds__(256, 2) qkv_gemm(
    const h16* __restrict__ Ah, const h16* __restrict__ Wbase,
    const float* __restrict__ bQ, const float* __restrict__ bK, const float* __restrict__ bV,
    h16* __restrict__ Cq, h16* __restrict__ Ck, h16* __restrict__ Cv)
{
    constexpr int ABYTES = 128 * 128;
    constexpr int STAGE  = 2 * ABYTES;

    extern __shared__ __align__(128) char smem[];
    const uint32_t sb = smem_u32(smem);
    const int tid = threadIdx.x, lane = tid & 31, wid = tid >> 5;
    const int wm = wid >> 1, wn = wid & 1;

    const int z = blockIdx.z;
    const int bm = blockIdx.y * 128;
    const int bn = blockIdx.x * 128;
    const h16* a0h = Ah + (ll)bm * ND;
    const h16* b0h = Wbase + (ll)z * ND * ND + (ll)bn * ND;
    const float* bias = (z == 0) ? bQ : (z == 1) ? bK : bV;

    float acc[2][8][4];
#pragma unroll
    for (int i = 0; i < 2; i++)
#pragma unroll
        for (int j = 0; j < 8; j++)
#pragma unroll
            for (int t = 0; t < 4; t++) acc[i][j][t] = 0.0f;

    const int aRow = (lane & 7) | (((lane >> 3) & 1) << 3);
    const int aC   = lane >> 4;
    const int bRow = (lane & 7) | (((lane >> 4) & 1) << 3);
    const int bC   = (lane >> 3) & 1;

    auto issue = [&](int c, int s) {
        const int k0 = c * 64;
        const uint32_t base = sb + s * STAGE;
#pragma unroll 4
        for (int u = tid; u < 2048; u += 256) {
            const int chunk = u & 7, row = u >> 3;
            const h16* src; uint32_t dbase; int r;
            if (row < 128) { src = a0h; r = row;       dbase = base;          }
            else           { src = b0h; r = row - 128; dbase = base + ABYTES; }
            cpasync16(dbase + swoff(r, chunk), src + (ll)r * ND + k0 + chunk * 8);
        }
    };

    issue(0, 0); cpcommit();
    issue(1, 1); cpcommit();

    int st = 0;
    for (int c = 0; c < 16; c++) {
        const int nxt = c + 2;
        if (nxt < 16) {
            int s2 = st + 2; if (s2 >= 3) s2 -= 3;
            issue(nxt, s2); cpcommit(); cpwait<2>();
        }
        else if (c + 1 < 16) { cpwait<1>(); }
        else                 { cpwait<0>(); }
        __syncthreads();

        const uint32_t tAh = sb + st * STAGE;
        const uint32_t tBh = tAh + ABYTES;

#pragma unroll
        for (int ks = 0; ks < 4; ks++) {
            uint32_t ah[2][4], bh[8][2];
#pragma unroll
            for (int mt = 0; mt < 2; mt++) {
                const int r = wm * 32 + mt * 16 + aRow;
                const int c16 = ks * 2 + aC;
                ldsm4(ah[mt][0], ah[mt][1], ah[mt][2], ah[mt][3], tAh + swoff(r, c16));
            }
#pragma unroll
            for (int nt2 = 0; nt2 < 4; nt2++) {
                const int r = wn * 64 + nt2 * 16 + bRow;
                const int c16 = ks * 2 + bC;
                ldsm4(bh[2*nt2][0], bh[2*nt2][1], bh[2*nt2+1][0], bh[2*nt2+1][1], tBh + swoff(r, c16));
            }
#pragma unroll
            for (int mt = 0; mt < 2; mt++)
#pragma unroll
                for (int nt = 0; nt < 8; nt++)
                    mma16816(acc[mt][nt], ah[mt], bh[nt]);
        }
        __syncthreads();
        st++; if (st >= 3) st = 0;
    }

    const int gid = lane >> 2, tig2 = (lane & 3) * 2;

    if (z < 2) {
        h16* Ch = (z == 0) ? Cq : Ck;
        const float sc = (z == 0) ? QSCL : 1.0f;
#pragma unroll
        for (int mt = 0; mt < 2; mt++)
#pragma unroll
            for (int nt = 0; nt < 8; nt++) {
                const int n = bn + wn * 64 + nt * 8 + tig2;
                const float bv0 = bias[n], bv1 = bias[n + 1];
#pragma unroll
                for (int hf = 0; hf < 2; hf++) {
                    const int m = bm + wm * 32 + mt * 16 + gid + hf * 8;
                    *reinterpret_cast<uint32_t*>(Ch + (ll)m * ND + n) =
                        packh((acc[mt][nt][hf * 2] + bv0) * sc,
                              (acc[mt][nt][hf * 2 + 1] + bv1) * sc);
                }
            }
    } else {
        constexpr int TSTRIDE = 272;
#pragma unroll
        for (int mt = 0; mt < 2; mt++)
#pragma unroll
            for (int nt = 0; nt < 8; nt++) {
                const int nl = wn * 64 + nt * 8 + tig2;
#pragma unroll
                for (int hf = 0; hf < 2; hf++) {
                    const int ml = wm * 32 + mt * 16 + gid + hf * 8;
                    *reinterpret_cast<h16*>(smem + nl * TSTRIDE + ml * 2) =
                        __float2half_rn(acc[mt][nt][hf * 2]);
                    *reinterpret_cast<h16*>(smem + (nl + 1) * TSTRIDE + ml * 2) =
                        __float2half_rn(acc[mt][nt][hf * 2 + 1]);
                }
            }
        __syncthreads();
        for (int u = tid; u < 128 * 16; u += 256) {
            const int nl = u >> 4, c16 = (u & 15) * 8;
            uint4 v = *reinterpret_cast<const uint4*>(smem + nl * TSTRIDE + c16 * 2);
            h16* hv = reinterpret_cast<h16*>(&v);
            const float bb = bias[bn + nl];
#pragma unroll
            for (int t = 0; t < 8; t++) hv[t] = __float2half_rn(__half2float(hv[t]) + bb);
            *reinterpret_cast<uint4*>(Cv + (ll)(bn + nl) * NBT + bm + c16) = v;
        }
    }
}

// ---------------- fused flash attention: no-max softmax, row-sums via ones-MMA ----------------
#define FSMEM 106496
__global__ void __launch_bounds__(256, 2) flash_kernel(
    const h16* __restrict__ Qh, const h16* __restrict__ Kh,
    const h16* __restrict__ Vt, h16* __restrict__ Oh)
{
    extern __shared__ __align__(128) char smem[];
    const uint32_t sb = smem_u32(smem);
    const int tid = threadIdx.x, lane = tid & 31, wid = tid >> 5;
    const int wm = wid >> 1, wn = wid & 1;
    const int qb = blockIdx.x;
    const int z = blockIdx.y, b = z >> 4, hh = z & 15;

    const h16* q0 = Qh + (ll)(b * NT + qb * 64) * ND + hh * 64;
    const h16* k0 = Kh + (ll)(b * NT) * ND + hh * 64;
    const h16* v0 = Vt + (ll)(hh * 64) * NBT + b * NT;

    for (int u = tid; u < 512; u += 256) {
        int r = u >> 3, c = u & 7;
        cpasync16(sb + swoff(r, c), q0 + (ll)r * ND + c * 8);
    }
    auto issueKV = [&](int t, int s) {
        const uint32_t kb = sb + 8192 + s * 32768;
        const uint32_t vb = kb + 16384;
        for (int u = tid; u < 1024; u += 256) {
            int r = u >> 3, c = u & 7;
            cpasync16(kb + swoff(r, c), k0 + (ll)(t * 128 + r) * ND + c * 8);
        }
        for (int u = tid; u < 1024; u += 256) {
            int half = u >> 9, r = (u >> 3) & 63, c = u & 7;
            cpasync16(vb + half * 8192 + swoff(r, c),
                      v0 + (ll)r * NBT + t * 128 + half * 64 + c * 8);
        }
    };
    issueKV(0, 0); cpcommit();
    issueKV(1, 1); cpcommit();

    const int aRow = (lane & 7) | (((lane >> 3) & 1) << 3);
    const int aC   = lane >> 4;
    const int bRow = (lane & 7) | (((lane >> 4) & 1) << 3);
    const int bC   = (lane >> 3) & 1;
    const int gid  = lane >> 2, tig2 = (lane & 3) * 2;

    float oacc[8][4];
#pragma unroll
    for (int j = 0; j < 8; j++)
#pragma unroll
        for (int t = 0; t < 4; t++) oacc[j][t] = 0.0f;
    float lacc[4] = {0.f, 0.f, 0.f, 0.f};
    const uint32_t onefrag[2] = {0x3C003C00u, 0x3C003C00u};

    int st = 0;
    for (int t = 0; t < 8; t++) {
        if (t + 2 < 8) {
            int s2 = st + 2; if (s2 >= 3) s2 -= 3;
            issueKV(t + 2, s2); cpcommit(); cpwait<2>();
        }
        else if (t + 1 < 8) { cpwait<1>(); }
        else                { cpwait<0>(); }
        __syncthreads();
        const uint32_t kb = sb + 8192 + st * 32768;
        const uint32_t vb = kb + 16384 + wn * 8192;

        float sacc[8][4];
#pragma unroll
        for (int j = 0; j < 8; j++)
#pragma unroll
            for (int u = 0; u < 4; u++) sacc[j][u] = 0.0f;

#pragma unroll
        for (int kc = 0; kc < 4; kc++) {
            uint32_t ah[4], bh[8][2];
            {
                const int r = wm * 16 + aRow;
                const int c16 = kc * 2 + aC;
                ldsm4(ah[0], ah[1], ah[2], ah[3], sb + swoff(r, c16));
            }
#pragma unroll
            for (int nt2 = 0; nt2 < 4; nt2++) {
                const int r = wn * 64 + nt2 * 16 + bRow;
                const int c16 = kc * 2 + bC;
                ldsm4(bh[2*nt2][0], bh[2*nt2][1], bh[2*nt2+1][0], bh[2*nt2+1][1], kb + swoff(r, c16));
            }
#pragma unroll
            for (int nt = 0; nt < 8; nt++)
                mma16816(sacc[nt], ah, bh[nt]);
        }

#pragma unroll
        for (int nt = 0; nt < 8; nt++)
#pragma unroll
            for (int j = 0; j < 4; j++)
                sacc[nt][j] = exp2f(sacc[nt][j]);

#pragma unroll
        for (int kk = 0; kk < 4; kk++) {
            uint32_t bfr[8][2];
#pragma unroll
            for (int dt2 = 0; dt2 < 4; dt2++) {
                const int r = dt2 * 16 + bRow;
                const int c16 = kk * 2 + bC;
                ldsm4(bfr[2*dt2][0], bfr[2*dt2][1], bfr[2*dt2+1][0], bfr[2*dt2+1][1], vb + swoff(r, c16));
            }
            uint32_t aH[4];
#pragma unroll
            for (int q = 0; q < 4; q++) {
                const int nt = 2 * kk + (q >> 1);
                const int j0 = (q & 1) * 2;
                aH[q] = packh(sacc[nt][j0], sacc[nt][j0 + 1]);
            }
#pragma unroll
            for (int dt = 0; dt < 8; dt++)
                mma16816(oacc[dt], aH, bfr[dt]);
            mma16816(lacc, aH, onefrag);
        }
        __syncthreads();
        st++; if (st >= 3) st = 0;
    }

    // ---- epilogue: sum the two wn halves; store reciprocal row sums ----
    float* lbuf = (float*)(smem + 104448);   // [2][64]
    float* lbt  = (float*)(smem + 104960);   // [64] (reciprocal)
    if ((lane & 3) == 0) {
#pragma unroll
        for (int hf = 0; hf < 2; hf++)
            lbuf[wn * 64 + wm * 16 + hf * 8 + gid] = lacc[hf * 2];
    }
    __syncthreads();
    if (wn == 0 && (lane & 3) == 0) {
#pragma unroll
        for (int hf = 0; hf < 2; hf++) {
            const int r = wm * 16 + hf * 8 + gid;
            lbt[r] = __frcp_rn(lbuf[r] + lbuf[64 + r]);
        }
    }

    float* obuf = (float*)smem;
    const int OST = 68;
    if (wn == 0) {
#pragma unroll
        for (int dt = 0; dt < 8; dt++)
#pragma unroll
            for (int j = 0; j < 4; j++)
                obuf[(wm*16 + (j>>1)*8 + gid) * OST + dt*8 + tig2 + (j&1)] = oacc[dt][j];
    }
    __syncthreads();
    if (wn == 1) {
#pragma unroll
        for (int dt = 0; dt < 8; dt++)
#pragma unroll
            for (int j = 0; j < 4; j++)
                obuf[(wm*16 + (j>>1)*8 + gid) * OST + dt*8 + tig2 + (j&1)] += oacc[dt][j];
    }
    __syncthreads();
    h16* oh = Oh + (ll)(b * NT + qb * 64) * ND + hh * 64;
    for (int u = tid; u < 4096; u += 256) {
        const int r = u >> 6, d = u & 63;
        oh[(ll)r * ND + d] = __float2half_rn(obuf[r * OST + d] * lbt[r]);
    }
}

// ---------------- batched weight transpose+convert (split-launchable via base) ----------------
struct WJob { const float* src; h16* dst; int K; int N; int start; };
struct WJobs { WJob e[13]; };

__global__ void __launch_bounds__(256) wsplit_all(WJobs jobs, int base) {
    __shared__ float t[32][33];
    int bx = blockIdx.x + base;
    int j = 0;
#pragma unroll
    for (int i = 0; i < 12; i++)
        if (bx >= jobs.e[i + 1].start) j = i + 1;
    const WJob& wj = jobs.e[j];
    const int ti = bx - wj.start;
    const int nb = wj.N / 32;
    const int n0 = (ti % nb) * 32, k0 = (ti / nb) * 32;
    const int tx = threadIdx.x, ty = threadIdx.y;
#pragma unroll
    for (int i = 0; i < 4; i++)
        t[ty + i * 8][tx] = wj.src[(ll)(k0 + ty + i * 8) * wj.N + n0 + tx];
    __syncthreads();
#pragma unroll
    for (int i = 0; i < 4; i++) {
        int n = ty + i * 8;
        wj.dst[(ll)(n0 + n) * wj.K + k0 + tx] = __float2half_rn(t[tx][n]);
    }
}

__global__ void concat_kernel(const float* __restrict__ hs, const float* __restrict__ mem) {
    int i4 = blockIdx.x * blockDim.x + threadIdx.x;
    if (i4 >= NBT * ND / 4) return;
    int idx = i4 * 4;
    int d = idx % ND;
    int t = (idx / ND) % NT;
    int b = idx / (ND * NT);
    float4 v = (t < NM) ? *reinterpret_cast<const float4*>(mem + t * ND + d)
                        : *reinterpret_cast<const float4*>(hs + ((size_t)(b * NS + t - NM)) * ND + d);
    *reinterpret_cast<float4*>(g_x + idx) = v;
    *reinterpret_cast<uint32_t*>(g_xh + idx)     = packh(v.x, v.y);
    *reinterpret_cast<uint32_t*>(g_xh + idx + 2) = packh(v.z, v.w);
}

// x = LN(y + x); y is h16
__global__ void __launch_bounds__(256) add_ln_kernel(const h16* __restrict__ y,
                                                     const float* __restrict__ gam,
                                                     const float* __restrict__ bet) {
    __shared__ float red[8];
    __shared__ float s0, s1;
    const int tid = threadIdx.x;
    const size_t base = (size_t)blockIdx.x * ND;
    const int c = tid * 4;
    union { uint2 u; h16 h[4]; } Y;
    Y.u = *reinterpret_cast<const uint2*>(y + base + c);
    float4 xo = *reinterpret_cast<const float4*>(g_x + base + c);
    float v0 = __half2float(Y.h[0]) + xo.x, v1 = __half2float(Y.h[1]) + xo.y;
    float v2 = __half2float(Y.h[2]) + xo.z, v3 = __half2float(Y.h[3]) + xo.w;
    float s = v0 + v1 + v2 + v3;
    for (int o = 16; o > 0; o >>= 1) s += __shfl_xor_sync(0xffffffffu, s, o);
    if ((tid & 31) == 0) red[tid >> 5] = s;
    __syncthreads();
    if (tid == 0) { float t = 0; for (int i = 0; i < 8; i++) t += red[i]; s0 = t * (1.0f / ND); }
    __syncthreads();
    const float mean = s0;
    float d0 = v0 - mean, d1 = v1 - mean, d2 = v2 - mean, d3 = v3 - mean;
    float vs = d0*d0 + d1*d1 + d2*d2 + d3*d3;
    for (int o = 16; o > 0; o >>= 1) vs += __shfl_xor_sync(0xffffffffu, vs, o);
    if ((tid & 31) == 0) red[tid >> 5] = vs;
    __syncthreads();
    if (tid == 0) { float t = 0; for (int i = 0; i < 8; i++) t += red[i]; s1 = rsqrtf(t * (1.0f / ND) + 1e-12f); }
    __syncthreads();
    const float inv = s1;
    float4 gv = *reinterpret_cast<const float4*>(gam + c);
    float4 bv = *reinterpret_cast<const float4*>(bet + c);
    float r0 = d0*inv*gv.x + bv.x, r1 = d1*inv*gv.y + bv.y;
    float r2 = d2*inv*gv.z + bv.z, r3 = d3*inv*gv.w + bv.w;
    *reinterpret_cast<float4*>(g_x + base + c) = make_float4(r0, r1, r2, r3);
    *reinterpret_cast<uint32_t*>(g_xh + base + c)     = packh(r0, r1);
    *reinterpret_cast<uint32_t*>(g_xh + base + c + 2) = packh(r2, r3);
}

__global__ void readout_kernel(float* __restrict__ out) {
    int idx = blockIdx.x * blockDim.x + threadIdx.x;
    if (idx >= NB * NM * ND) return;
    int d = idx % ND;
    int t = (idx / ND) % NM;
    int b = idx / (ND * NM);
    out[(size_t)NB * NS * NOUT + idx] = g_x[((size_t)b * NT + t) * ND + d];
}

#define S128 (3 * (128 * 128 + 128 * 128))   // 98304 (3-stage)

extern "C" void kernel_launch(void* const* d_in, const int* in_sizes, int n_in,
                              void* d_out, int out_size) {
    const float* hs   = (const float*)d_in[0];
    const float* mem  = (const float*)d_in[1];
    const float* Wq   = (const float*)d_in[2];
    const float* bq   = (const float*)d_in[3];
    const float* Wk   = (const float*)d_in[4];
    const float* bk   = (const float*)d_in[5];
    const float* Wv   = (const float*)d_in[6];
    const float* bv   = (const float*)d_in[7];
    const float* Wo   = (const float*)d_in[8];
    const float* bo   = (const float*)d_in[9];
    const float* ln1g = (const float*)d_in[10];
    const float* ln1b = (const float*)d_in[11];
    const float* Wm   = (const float*)d_in[12];
    const float* bmv  = (const float*)d_in[13];
    const float* Wr   = (const float*)d_in[14];
    const float* br   = (const float*)d_in[15];
    const float* ln2g = (const float*)d_in[16];
    const float* ln2b = (const float*)d_in[17];
    const float* Wp   = (const float*)d_in[18];
    const float* bp   = (const float*)d_in[19];
    float* out = (float*)d_out;

    static h16 *wh = nullptr, *xh, *qh, *kh, *vth, *t0h, *ih;
    static cudaStream_t s1 = 0;
    static cudaEvent_t ev0 = nullptr, ev1 = nullptr;
    if (!wh) {
        cudaGetSymbolAddress((void**)&wh, g_wh);
        cudaGetSymbolAddress((void**)&xh, g_xh);
        cudaGetSymbolAddress((void**)&qh, g_qh);
        cudaGetSymbolAddress((void**)&kh, g_kh);
        cudaGetSymbolAddress((void**)&vth, g_vth);
        cudaGetSymbolAddress((void**)&t0h, g_t0h);
        cudaGetSymbolAddress((void**)&ih, g_ih);
        cudaFuncSetAttribute((const void*)tgemm<128,0,1>, cudaFuncAttributeMaxDynamicSharedMemorySize, S128);
        cudaFuncSetAttribute((const void*)tgemm<128,1,1>, cudaFuncAttributeMaxDynamicSharedMemorySize, S128);
        cudaFuncSetAttribute((const void*)tgemm<128,1,0>, cudaFuncAttributeMaxDynamicSharedMemorySize, S128);
        cudaFuncSetAttribute((const void*)qkv_gemm, cudaFuncAttributeMaxDynamicSharedMemorySize, S128);
        cudaFuncSetAttribute((const void*)flash_kernel, cudaFuncAttributeMaxDynamicSharedMemorySize, FSMEM);
        if (cudaStreamCreateWithFlags(&s1, cudaStreamNonBlocking) != cudaSuccess) s1 = 0;
        if (cudaEventCreateWithFlags(&ev0, cudaEventDisableTiming) != cudaSuccess) ev0 = nullptr;
        if (cudaEventCreateWithFlags(&ev1, cudaEventDisableTiming) != cudaSuccess) ev1 = nullptr;
    }
    const bool fork = (s1 != 0) && ev0 && ev1;

    const ll Z = 0;
    const ll DD = (ll)ND * ND;
    dim3 t32(32, 8);

    WJobs jobs;
    int startA = 0, total = 0;
    {
        int start = 0, j = 0;
        const float* csrc[3] = { Wq, Wk, Wv };
        for (int i = 0; i < 3; i++) {
            jobs.e[j] = { csrc[i], wh + (ll)i * DD, ND, ND, start };
            start += 1024; j++;
        }
        startA = start;
        jobs.e[j] = { Wo, wh + 3*DD, ND, ND, start };                       start += 1024; j++;
        jobs.e[j] = { Wm, wh + 4*DD, ND, NI, start };                       start += 4096; j++;
        jobs.e[j] = { Wr, wh + 4*DD + (ll)ND*NI, NI, ND, start };           start += 4096; j++;
        {
            ll o = WPL;
            const float* srcs[6] = { Wq + DD, Wk + DD, Wv + DD, Wo + DD,
                                     Wm + (ll)ND*NI, Wr + (ll)NI*ND };
            h16* dsts[6] = { wh + o, wh + o + DD, wh + o + 2*DD, wh + o + 3*DD,
                             wh + o + 4*DD, wh + o + 4*DD + (ll)ND*NI };
            int Ks[6] = { ND, ND, ND, ND, ND, NI };
            int Ns[6] = { ND, ND, ND, ND, NI, ND };
            for (int i = 0; i < 6; i++) {
                jobs.e[j] = { srcs[i], dsts[i], Ks[i], Ns[i], start };
                start += (Ks[i] / 32) * (Ns[i] / 32); j++;
            }
        }
        jobs.e[j] = { Wp, wh + (ll)NL*WPL, ND, NOUT, start };
        start += (ND / 32) * (NOUT / 32);
        total = start;
    }

    wsplit_all<<<startA, t32>>>(jobs, 0);
    if (fork) {
        cudaEventRecord(ev0, 0);
        cudaStreamWaitEvent(s1, ev0, 0);
        wsplit_all<<<total - startA, t32, 0, s1>>>(jobs, startA);
        cudaEventRecord(ev1, s1);
    } else {
        wsplit_all<<<total - startA, t32>>>(jobs, startA);
    }

    concat_kernel<<<(NBT * ND / 4 + 255) / 256, 256>>>(hs, mem);

    for (int l = 0; l < NL; l++) {
        ll o = (ll)l * WPL;
        const h16 *wqkv = wh + o;
        const h16 *woh = wh + o + 3*DD;
        const h16 *wmh = wh + o + 4*DD;
        const h16 *wrh = wh + o + 4*DD + (ll)ND*NI;

        qkv_gemm<<<dim3(8, 32, 3), 256, S128>>>(xh, wqkv,
            bq + l*ND, bk + l*ND, bv + l*ND, qh, kh, vth);

        flash_kernel<<<dim3(16, 64), 256, FSMEM>>>(qh, kh, vth, t0h);

        if (l == 0 && fork) cudaStreamWaitEvent(0, ev1, 0);

        tgemm<128,0,1><<<dim3(8, 32, 1), 256, S128>>>(t0h, woh, bo + l*ND, 1.f,
            nullptr, kh, ND, ND, ND, ND, Z,Z,Z,Z,Z,Z, 1);
        add_ln_kernel<<<NBT, 256>>>(kh, ln1g + l*ND, ln1b + l*ND);

        tgemm<128,1,1><<<dim3(32, 32, 1), 256, S128>>>(xh, wmh, bmv + l*NI, 1.f,
            nullptr, ih, ND, ND, ND, NI, Z,Z,Z,Z,Z,Z, 1);
        tgemm<128,0,1><<<dim3(8, 32, 1), 256, S128>>>(ih, wrh, br + l*ND, 1.f,
            nullptr, kh, NI, NI, NI, ND, Z,Z,Z,Z,Z,Z, 1);
        add_ln_kernel<<<NBT, 256>>>(kh, ln2g + l*ND, ln2b + l*ND);
    }

    tgemm<128,1,0><<<dim3(32, 7, NB), 256, S128>>>(xh + NM*ND,
        wh + (ll)NL*WPL, bp, 1.f,
        out, nullptr, ND, ND, ND, NOUT,
        (ll)NT*ND, Z, Z, Z, (ll)NS*NOUT, Z, 1);

    readout_kernel<<<(NB * NM * ND + 255) / 256, 256>>>(out);
}

// round 17
// speedup vs baseline: 1.0086x; 1.0086x over previous
#include <cuda_runtime.h>
#include <cuda_fp16.h>
#include <math.h>
#include <stdint.h>

#define NB   4
#define NS   896
#define ND   1024
#define NH   16
#define NDH  64
#define NI   4096
#define NOUT 4096
#define NL   2
#define NM   128
#define NT   1024
#define NBT  4096

typedef __half h16;
typedef long long ll;

__device__ float g_x[NBT * ND];
__device__ h16  g_xh[NBT * ND];
__device__ h16  g_qh[NBT * ND];
__device__ h16  g_kh[NBT * ND];     // K for flash; then reused as h16 residual y
__device__ h16  g_vth[NBT * ND];
__device__ h16  g_t0h[NBT * ND];
__device__ h16  g_ih[(size_t)NBT * NI];
#define WPL (4 * ND * ND + ND * NI + NI * ND)
#define WELEMS (NL * WPL + ND * NOUT)
__device__ h16  g_wh[WELEMS];

__device__ __forceinline__ uint32_t smem_u32(const void* p) {
    uint32_t a;
    asm("{ .reg .u64 t; cvta.to.shared.u64 t, %1; cvt.u32.u64 %0, t; }" : "=r"(a) : "l"(p));
    return a;
}
__device__ __forceinline__ float gelu_f(float x) {
    return 0.5f * x * (1.0f + erff(x * 0.7071067811865476f));
}
__device__ __forceinline__ void ldsm4(uint32_t& r0, uint32_t& r1, uint32_t& r2, uint32_t& r3, uint32_t a) {
    asm volatile("ldmatrix.sync.aligned.m8n8.x4.shared.b16 {%0,%1,%2,%3}, [%4];"
                 : "=r"(r0), "=r"(r1), "=r"(r2), "=r"(r3) : "r"(a));
}
__device__ __forceinline__ void mma16816(float* c, const uint32_t* a, const uint32_t* b) {
    asm volatile("mma.sync.aligned.m16n8k16.row.col.f32.f16.f16.f32 "
                 "{%0,%1,%2,%3},{%4,%5,%6,%7},{%8,%9},{%0,%1,%2,%3};"
                 : "+f"(c[0]), "+f"(c[1]), "+f"(c[2]), "+f"(c[3])
                 : "r"(a[0]), "r"(a[1]), "r"(a[2]), "r"(a[3]), "r"(b[0]), "r"(b[1]));
}
__device__ __forceinline__ void cpasync16(uint32_t dst, const void* src) {
    asm volatile("cp.async.cg.shared.global [%0], [%1], 16;" :: "r"(dst), "l"(src));
}
__device__ __forceinline__ void cpcommit() { asm volatile("cp.async.commit_group;" ::: "memory"); }
template<int N> __device__ __forceinline__ void cpwait() {
    asm volatile("cp.async.wait_group %0;" :: "n"(N) : "memory");
}
__device__ __forceinline__ uint32_t swoff(int r, int c16) {
    return (uint32_t)(r * 128 + ((c16 ^ (r & 7)) * 16));
}
__device__ __forceinline__ uint32_t packh(float a, float b) {
    uint32_t r;
    asm("cvt.rn.f16x2.f32 %0, %1, %2;" : "=r"(r) : "f"(b), "f"(a));
    return r;
}

// ---------------- fp16 warp-MMA GEMM (R8/R15 schedule: 2-stage, preloaded B frags) ----------------
template<int BN, int ACT, int OUTM>
__global__ void __launch_bounds__(256, 2) tgemm(
    const h16* __restrict__ Ah, const h16* __restrict__ Bh,
    const float* __restrict__ bias, float alpha,
    float* __restrict__ Cf, h16* __restrict__ Ch,
    int K, int lda, int ldb, int ldc,
    ll oA, ll iA, ll oB, ll iB, ll oC, ll iC, int h)
{
    constexpr int ABYTES = 128 * 128;
    constexpr int BBYTES = BN * 128;
    constexpr int STAGE  = ABYTES + BBYTES;
    constexpr int WN     = BN / 2;
    constexpr int NT8    = WN / 8;

    extern __shared__ __align__(128) char smem[];
    const uint32_t sb = smem_u32(smem);
    const int tid = threadIdx.x, lane = tid & 31, wid = tid >> 5;
    const int wm = wid >> 1, wn = wid & 1;

    const int z = blockIdx.z;
    const ll aoff = (ll)(z / h) * oA + (ll)(z % h) * iA;
    const ll boff = (ll)(z / h) * oB + (ll)(z % h) * iB;
    const ll coff = (ll)(z / h) * oC + (ll)(z % h) * iC;
    const int bm = blockIdx.y * 128;
    const int bn = blockIdx.x * BN;
    const h16* a0h = Ah + aoff + (ll)bm * lda;
    const h16* b0h = Bh + boff + (ll)bn * ldb;

    float acc[2][NT8][4];
#pragma unroll
    for (int i = 0; i < 2; i++)
#pragma unroll
        for (int j = 0; j < NT8; j++)
#pragma unroll
            for (int t = 0; t < 4; t++) acc[i][j][t] = 0.0f;

    const int nch = K >> 6;
    const int aRow = (lane & 7) | (((lane >> 3) & 1) << 3);
    const int aC   = lane >> 4;
    const int bRow = (lane & 7) | (((lane >> 4) & 1) << 3);
    const int bC   = (lane >> 3) & 1;

    auto issue = [&](int c, int s) {
        const int k0 = c * 64;
        const uint32_t base = sb + s * STAGE;
        constexpr int TOT = (128 + BN) * 8;
#pragma unroll 4
        for (int u = tid; u < TOT; u += 256) {
            const int chunk = u & 7, row = u >> 3;
            const h16* src; uint32_t dbase; int r, ld;
            if (row < 128) { src = a0h; r = row;       dbase = base;          ld = lda; }
            else           { src = b0h; r = row - 128; dbase = base + ABYTES; ld = ldb; }
            cpasync16(dbase + swoff(r, chunk), src + (ll)r * ld + k0 + chunk * 8);
        }
    };

    issue(0, 0);
    cpcommit();

    for (int c = 0; c < nch; c++) {
        if (c + 1 < nch) { issue(c + 1, (c + 1) & 1); cpcommit(); cpwait<1>(); }
        else             { cpwait<0>(); }
        __syncthreads();

        const uint32_t tAh = sb + (c & 1) * STAGE;
        const uint32_t tBh = tAh + ABYTES;

#pragma unroll
        for (int ks = 0; ks < 4; ks++) {
            uint32_t ah[2][4], bh[NT8][2];
#pragma unroll
            for (int mt = 0; mt < 2; mt++) {
                const int r = wm * 32 + mt * 16 + aRow;
                const int c16 = ks * 2 + aC;
                ldsm4(ah[mt][0], ah[mt][1], ah[mt][2], ah[mt][3], tAh + swoff(r, c16));
            }
#pragma unroll
            for (int nt2 = 0; nt2 < NT8 / 2; nt2++) {
                const int r = wn * WN + nt2 * 16 + bRow;
                const int c16 = ks * 2 + bC;
                ldsm4(bh[2*nt2][0], bh[2*nt2][1], bh[2*nt2+1][0], bh[2*nt2+1][1], tBh + swoff(r, c16));
            }
#pragma unroll
            for (int mt = 0; mt < 2; mt++)
#pragma unroll
                for (int nt = 0; nt < NT8; nt++)
                    mma16816(acc[mt][nt], ah[mt], bh[nt]);
        }
        __syncthreads();
    }

    const int gid = lane >> 2, tig2 = (lane & 3) * 2;

#pragma unroll
    for (int mt = 0; mt < 2; mt++) {
#pragma unroll
        for (int nt = 0; nt < NT8; nt++) {
            const int n = bn + wn * WN + nt * 8 + tig2;
            float bv0 = 0.f, bv1 = 0.f;
            if (bias) { bv0 = bias[n]; bv1 = bias[n + 1]; }
#pragma unroll
            for (int hf = 0; hf < 2; hf++) {
                const int m = bm + wm * 32 + mt * 16 + gid + hf * 8;
                float v0 = acc[mt][nt][hf * 2]     * alpha + bv0;
                float v1 = acc[mt][nt][hf * 2 + 1] * alpha + bv1;
                if (ACT) { v0 = gelu_f(v0); v1 = gelu_f(v1); }
                if (OUTM == 0) {
                    *reinterpret_cast<float2*>(Cf + coff + (ll)m * ldc + n) = make_float2(v0, v1);
                } else {
                    *reinterpret_cast<uint32_t*>(Ch + coff + (ll)m * ldc + n) = packh(v0, v1);
                }
            }
        }
    }
}

#define QSCL 0.18033688011112042f   // 0.125 * log2(e), folded into Q projection

// ---------------- fused QKV projection: grid (8, 32, 3), 2-stage ----------------
__global__ void __launch_bounds__(256, 2) qkv_gemm(
    const h16* __restrict__ Ah, const h16* __restrict__ Wbase,
    const float* __restrict__ bQ, const float* __restrict__ bK, const float* __restrict__ bV,
    h16* __restrict__ Cq, h16* __restrict__ Ck, h16* __restrict__ Cv)
{
    constexpr int ABYTES = 128 * 128;
    constexpr int STAGE  = 2 * ABYTES;

    extern __shared__ __align__(128) char smem[];
    const uint32_t sb = smem_u32(smem);
    const int tid = threadIdx.x, lane = tid & 31, wid = tid >> 5;
    const int wm = wid >> 1, wn = wid & 1;

    const int z = blockIdx.z;
    const int bm = blockIdx.y * 128;
    const int bn = blockIdx.x * 128;
    const h16* a0h = Ah + (ll)bm * ND;
    const h16* b0h = Wbase + (ll)z * ND * ND + (ll)bn * ND;
    const float* bias = (z == 0) ? bQ : (z == 1) ? bK : bV;

    float acc[2][8][4];
#pragma unroll
    for (int i = 0; i < 2; i++)
#pragma unroll
        for (int j = 0; j < 8; j++)
#pragma unroll
            for (int t = 0; t < 4; t++) acc[i][j][t] = 0.0f;

    const int aRow = (lane & 7) | (((lane >> 3) & 1) << 3);
    const int aC   = lane >> 4;
    const int bRow = (lane & 7) | (((lane >> 4) & 1) << 3);
    const int bC   = (lane >> 3) & 1;

    auto issue = [&](int c, int s) {
        const int k0 = c * 64;
        const uint32_t base = sb + s * STAGE;
#pragma unroll 4
        for (int u = tid; u < 2048; u += 256) {
            const int chunk = u & 7, row = u >> 3;
            const h16* src; uint32_t dbase; int r;
            if (row < 128) { src = a0h; r = row;       dbase = base;          }
            else           { src = b0h; r = row - 128; dbase = base + ABYTES; }
            cpasync16(dbase + swoff(r, chunk), src + (ll)r * ND + k0 + chunk * 8);
        }
    };

    issue(0, 0);
    cpcommit();

    for (int c = 0; c < 16; c++) {
        if (c + 1 < 16) { issue(c + 1, (c + 1) & 1); cpcommit(); cpwait<1>(); }
        else            { cpwait<0>(); }
        __syncthreads();

        const uint32_t tAh = sb + (c & 1) * STAGE;
        const uint32_t tBh = tAh + ABYTES;

#pragma unroll
        for (int ks = 0; ks < 4; ks++) {
            uint32_t ah[2][4], bh[8][2];
#pragma unroll
            for (int mt = 0; mt < 2; mt++) {
                const int r = wm * 32 + mt * 16 + aRow;
                const int c16 = ks * 2 + aC;
                ldsm4(ah[mt][0], ah[mt][1], ah[mt][2], ah[mt][3], tAh + swoff(r, c16));
            }
#pragma unroll
            for (int nt2 = 0; nt2 < 4; nt2++) {
                const int r = wn * 64 + nt2 * 16 + bRow;
                const int c16 = ks * 2 + bC;
                ldsm4(bh[2*nt2][0], bh[2*nt2][1], bh[2*nt2+1][0], bh[2*nt2+1][1], tBh + swoff(r, c16));
            }
#pragma unroll
            for (int mt = 0; mt < 2; mt++)
#pragma unroll
                for (int nt = 0; nt < 8; nt++)
                    mma16816(acc[mt][nt], ah[mt], bh[nt]);
        }
        __syncthreads();
    }

    const int gid = lane >> 2, tig2 = (lane & 3) * 2;

    if (z < 2) {
        h16* Ch = (z == 0) ? Cq : Ck;
        const float sc = (z == 0) ? QSCL : 1.0f;
#pragma unroll
        for (int mt = 0; mt < 2; mt++)
#pragma unroll
            for (int nt = 0; nt < 8; nt++) {
                const int n = bn + wn * 64 + nt * 8 + tig2;
                const float bv0 = bias[n], bv1 = bias[n + 1];
#pragma unroll
                for (int hf = 0; hf < 2; hf++) {
                    const int m = bm + wm * 32 + mt * 16 + gid + hf * 8;
                    *reinterpret_cast<uint32_t*>(Ch + (ll)m * ND + n) =
                        packh((acc[mt][nt][hf * 2] + bv0) * sc,
                              (acc[mt][nt][hf * 2 + 1] + bv1) * sc);
                }
            }
    } else {
        constexpr int TSTRIDE = 272;
#pragma unroll
        for (int mt = 0; mt < 2; mt++)
#pragma unroll
            for (int nt = 0; nt < 8; nt++) {
                const int nl = wn * 64 + nt * 8 + tig2;
#pragma unroll
                for (int hf = 0; hf < 2; hf++) {
                    const int ml = wm * 32 + mt * 16 + gid + hf * 8;
                    *reinterpret_cast<h16*>(smem + nl * TSTRIDE + ml * 2) =
                        __float2half_rn(acc[mt][nt][hf * 2]);
                    *reinterpret_cast<h16*>(smem + (nl + 1) * TSTRIDE + ml * 2) =
                        __float2half_rn(acc[mt][nt][hf * 2 + 1]);
                }
            }
        __syncthreads();
        for (int u = tid; u < 128 * 16; u += 256) {
            const int nl = u >> 4, c16 = (u & 15) * 8;
            uint4 v = *reinterpret_cast<const uint4*>(smem + nl * TSTRIDE + c16 * 2);
            h16* hv = reinterpret_cast<h16*>(&v);
            const float bb = bias[bn + nl];
#pragma unroll
            for (int t = 0; t < 8; t++) hv[t] = __float2half_rn(__half2float(hv[t]) + bb);
            *reinterpret_cast<uint4*>(Cv + (ll)(bn + nl) * NBT + bm + c16) = v;
        }
    }
}

// ---------------- fused flash attention: no-max softmax, row-sums via ones-MMA ----------------
#define FSMEM 106496
__global__ void __launch_bounds__(256, 2) flash_kernel(
    const h16* __restrict__ Qh, const h16* __restrict__ Kh,
    const h16* __restrict__ Vt, h16* __restrict__ Oh)
{
    extern __shared__ __align__(128) char smem[];
    const uint32_t sb = smem_u32(smem);
    const int tid = threadIdx.x, lane = tid & 31, wid = tid >> 5;
    const int wm = wid >> 1, wn = wid & 1;
    const int qb = blockIdx.x;
    const int z = blockIdx.y, b = z >> 4, hh = z & 15;

    const h16* q0 = Qh + (ll)(b * NT + qb * 64) * ND + hh * 64;
    const h16* k0 = Kh + (ll)(b * NT) * ND + hh * 64;
    const h16* v0 = Vt + (ll)(hh * 64) * NBT + b * NT;

    for (int u = tid; u < 512; u += 256) {
        int r = u >> 3, c = u & 7;
        cpasync16(sb + swoff(r, c), q0 + (ll)r * ND + c * 8);
    }
    auto issueKV = [&](int t, int s) {
        const uint32_t kb = sb + 8192 + s * 32768;
        const uint32_t vb = kb + 16384;
        for (int u = tid; u < 1024; u += 256) {
            int r = u >> 3, c = u & 7;
            cpasync16(kb + swoff(r, c), k0 + (ll)(t * 128 + r) * ND + c * 8);
        }
        for (int u = tid; u < 1024; u += 256) {
            int half = u >> 9, r = (u >> 3) & 63, c = u & 7;
            cpasync16(vb + half * 8192 + swoff(r, c),
                      v0 + (ll)r * NBT + t * 128 + half * 64 + c * 8);
        }
    };
    issueKV(0, 0); cpcommit();
    issueKV(1, 1); cpcommit();

    const int aRow = (lane & 7) | (((lane >> 3) & 1) << 3);
    const int aC   = lane >> 4;
    const int bRow = (lane & 7) | (((lane >> 4) & 1) << 3);
    const int bC   = (lane >> 3) & 1;
    const int gid  = lane >> 2, tig2 = (lane & 3) * 2;

    float oacc[8][4];
#pragma unroll
    for (int j = 0; j < 8; j++)
#pragma unroll
        for (int t = 0; t < 4; t++) oacc[j][t] = 0.0f;
    float lacc[4] = {0.f, 0.f, 0.f, 0.f};
    const uint32_t onefrag[2] = {0x3C003C00u, 0x3C003C00u};

    int st = 0;
    for (int t = 0; t < 8; t++) {
        if (t + 2 < 8) {
            int s2 = st + 2; if (s2 >= 3) s2 -= 3;
            issueKV(t + 2, s2); cpcommit(); cpwait<2>();
        }
        else if (t + 1 < 8) { cpwait<1>(); }
        else                { cpwait<0>(); }
        __syncthreads();
        const uint32_t kb = sb + 8192 + st * 32768;
        const uint32_t vb = kb + 16384 + wn * 8192;

        float sacc[8][4];
#pragma unroll
        for (int j = 0; j < 8; j++)
#pragma unroll
            for (int u = 0; u < 4; u++) sacc[j][u] = 0.0f;

#pragma unroll
        for (int kc = 0; kc < 4; kc++) {
            uint32_t ah[4], bh[8][2];
            {
                const int r = wm * 16 + aRow;
                const int c16 = kc * 2 + aC;
                ldsm4(ah[0], ah[1], ah[2], ah[3], sb + swoff(r, c16));
            }
#pragma unroll
            for (int nt2 = 0; nt2 < 4; nt2++) {
                const int r = wn * 64 + nt2 * 16 + bRow;
                const int c16 = kc * 2 + bC;
                ldsm4(bh[2*nt2][0], bh[2*nt2][1], bh[2*nt2+1][0], bh[2*nt2+1][1], kb + swoff(r, c16));
            }
#pragma unroll
            for (int nt = 0; nt < 8; nt++)
                mma16816(sacc[nt], ah, bh[nt]);
        }

#pragma unroll
        for (int nt = 0; nt < 8; nt++)
#pragma unroll
            for (int j = 0; j < 4; j++)
                sacc[nt][j] = exp2f(sacc[nt][j]);

#pragma unroll
        for (int kk = 0; kk < 4; kk++) {
            uint32_t bfr[8][2];
#pragma unroll
            for (int dt2 = 0; dt2 < 4; dt2++) {
                const int r = dt2 * 16 + bRow;
                const int c16 = kk * 2 + bC;
                ldsm4(bfr[2*dt2][0], bfr[2*dt2][1], bfr[2*dt2+1][0], bfr[2*dt2+1][1], vb + swoff(r, c16));
            }
            uint32_t aH[4];
#pragma unroll
            for (int q = 0; q < 4; q++) {
                const int nt = 2 * kk + (q >> 1);
                const int j0 = (q & 1) * 2;
                aH[q] = packh(sacc[nt][j0], sacc[nt][j0 + 1]);
            }
#pragma unroll
            for (int dt = 0; dt < 8; dt++)
                mma16816(oacc[dt], aH, bfr[dt]);
            mma16816(lacc, aH, onefrag);
        }
        __syncthreads();
        st++; if (st >= 3) st = 0;
    }

    // ---- epilogue: sum the two wn halves; store reciprocal row sums ----
    float* lbuf = (float*)(smem + 104448);   // [2][64]
    float* lbt  = (float*)(smem + 104960);   // [64] (reciprocal)
    if ((lane & 3) == 0) {
#pragma unroll
        for (int hf = 0; hf < 2; hf++)
            lbuf[wn * 64 + wm * 16 + hf * 8 + gid] = lacc[hf * 2];
    }
    __syncthreads();
    if (wn == 0 && (lane & 3) == 0) {
#pragma unroll
        for (int hf = 0; hf < 2; hf++) {
            const int r = wm * 16 + hf * 8 + gid;
            lbt[r] = __frcp_rn(lbuf[r] + lbuf[64 + r]);
        }
    }

    float* obuf = (float*)smem;
    const int OST = 68;
    if (wn == 0) {
#pragma unroll
        for (int dt = 0; dt < 8; dt++)
#pragma unroll
            for (int j = 0; j < 4; j++)
                obuf[(wm*16 + (j>>1)*8 + gid) * OST + dt*8 + tig2 + (j&1)] = oacc[dt][j];
    }
    __syncthreads();
    if (wn == 1) {
#pragma unroll
        for (int dt = 0; dt < 8; dt++)
#pragma unroll
            for (int j = 0; j < 4; j++)
                obuf[(wm*16 + (j>>1)*8 + gid) * OST + dt*8 + tig2 + (j&1)] += oacc[dt][j];
    }
    __syncthreads();
    h16* oh = Oh + (ll)(b * NT + qb * 64) * ND + hh * 64;
    for (int u = tid; u < 4096; u += 256) {
        const int r = u >> 6, d = u & 63;
        oh[(ll)r * ND + d] = __float2half_rn(obuf[r * OST + d] * lbt[r]);
    }
}

// ---------------- batched weight transpose+convert (split-launchable via base) ----------------
struct WJob { const float* src; h16* dst; int K; int N; int start; };
struct WJobs { WJob e[13]; };

__global__ void __launch_bounds__(256) wsplit_all(WJobs jobs, int base) {
    __shared__ float t[32][33];
    int bx = blockIdx.x + base;
    int j = 0;
#pragma unroll
    for (int i = 0; i < 12; i++)
        if (bx >= jobs.e[i + 1].start) j = i + 1;
    const WJob& wj = jobs.e[j];
    const int ti = bx - wj.start;
    const int nb = wj.N / 32;
    const int n0 = (ti % nb) * 32, k0 = (ti / nb) * 32;
    const int tx = threadIdx.x, ty = threadIdx.y;
#pragma unroll
    for (int i = 0; i < 4; i++)
        t[ty + i * 8][tx] = wj.src[(ll)(k0 + ty + i * 8) * wj.N + n0 + tx];
    __syncthreads();
#pragma unroll
    for (int i = 0; i < 4; i++) {
        int n = ty + i * 8;
        wj.dst[(ll)(n0 + n) * wj.K + k0 + tx] = __float2half_rn(t[tx][n]);
    }
}

__global__ void concat_kernel(const float* __restrict__ hs, const float* __restrict__ mem) {
    int i4 = blockIdx.x * blockDim.x + threadIdx.x;
    if (i4 >= NBT * ND / 4) return;
    int idx = i4 * 4;
    int d = idx % ND;
    int t = (idx / ND) % NT;
    int b = idx / (ND * NT);
    float4 v = (t < NM) ? *reinterpret_cast<const float4*>(mem + t * ND + d)
                        : *reinterpret_cast<const float4*>(hs + ((size_t)(b * NS + t - NM)) * ND + d);
    *reinterpret_cast<float4*>(g_x + idx) = v;
    *reinterpret_cast<uint32_t*>(g_xh + idx)     = packh(v.x, v.y);
    *reinterpret_cast<uint32_t*>(g_xh + idx + 2) = packh(v.z, v.w);
}

// x = LN(y + x); y is h16
__global__ void __launch_bounds__(256) add_ln_kernel(const h16* __restrict__ y,
                                                     const float* __restrict__ gam,
                                                     const float* __restrict__ bet) {
    __shared__ float red[8];
    __shared__ float s0, s1;
    const int tid = threadIdx.x;
    const size_t base = (size_t)blockIdx.x * ND;
    const int c = tid * 4;
    union { uint2 u; h16 h[4]; } Y;
    Y.u = *reinterpret_cast<const uint2*>(y + base + c);
    float4 xo = *reinterpret_cast<const float4*>(g_x + base + c);
    float v0 = __half2float(Y.h[0]) + xo.x, v1 = __half2float(Y.h[1]) + xo.y;
    float v2 = __half2float(Y.h[2]) + xo.z, v3 = __half2float(Y.h[3]) + xo.w;
    float s = v0 + v1 + v2 + v3;
    for (int o = 16; o > 0; o >>= 1) s += __shfl_xor_sync(0xffffffffu, s, o);
    if ((tid & 31) == 0) red[tid >> 5] = s;
    __syncthreads();
    if (tid == 0) { float t = 0; for (int i = 0; i < 8; i++) t += red[i]; s0 = t * (1.0f / ND); }
    __syncthreads();
    const float mean = s0;
    float d0 = v0 - mean, d1 = v1 - mean, d2 = v2 - mean, d3 = v3 - mean;
    float vs = d0*d0 + d1*d1 + d2*d2 + d3*d3;
    for (int o = 16; o > 0; o >>= 1) vs += __shfl_xor_sync(0xffffffffu, vs, o);
    if ((tid & 31) == 0) red[tid >> 5] = vs;
    __syncthreads();
    if (tid == 0) { float t = 0; for (int i = 0; i < 8; i++) t += red[i]; s1 = rsqrtf(t * (1.0f / ND) + 1e-12f); }
    __syncthreads();
    const float inv = s1;
    float4 gv = *reinterpret_cast<const float4*>(gam + c);
    float4 bv = *reinterpret_cast<const float4*>(bet + c);
    float r0 = d0*inv*gv.x + bv.x, r1 = d1*inv*gv.y + bv.y;
    float r2 = d2*inv*gv.z + bv.z, r3 = d3*inv*gv.w + bv.w;
    *reinterpret_cast<float4*>(g_x + base + c) = make_float4(r0, r1, r2, r3);
    *reinterpret_cast<uint32_t*>(g_xh + base + c)     = packh(r0, r1);
    *reinterpret_cast<uint32_t*>(g_xh + base + c + 2) = packh(r2, r3);
}

__global__ void readout_kernel(float* __restrict__ out) {
    int idx = blockIdx.x * blockDim.x + threadIdx.x;
    if (idx >= NB * NM * ND) return;
    int d = idx % ND;
    int t = (idx / ND) % NM;
    int b = idx / (ND * NM);
    out[(size_t)NB * NS * NOUT + idx] = g_x[((size_t)b * NT + t) * ND + d];
}

#define S128 (2 * (128 * 128 + 128 * 128))   // 65536 (2-stage)

extern "C" void kernel_launch(void* const* d_in, const int* in_sizes, int n_in,
                              void* d_out, int out_size) {
    const float* hs   = (const float*)d_in[0];
    const float* mem  = (const float*)d_in[1];
    const float* Wq   = (const float*)d_in[2];
    const float* bq   = (const float*)d_in[3];
    const float* Wk   = (const float*)d_in[4];
    const float* bk   = (const float*)d_in[5];
    const float* Wv   = (const float*)d_in[6];
    const float* bv   = (const float*)d_in[7];
    const float* Wo   = (const float*)d_in[8];
    const float* bo   = (const float*)d_in[9];
    const float* ln1g = (const float*)d_in[10];
    const float* ln1b = (const float*)d_in[11];
    const float* Wm   = (const float*)d_in[12];
    const float* bmv  = (const float*)d_in[13];
    const float* Wr   = (const float*)d_in[14];
    const float* br   = (const float*)d_in[15];
    const float* ln2g = (const float*)d_in[16];
    const float* ln2b = (const float*)d_in[17];
    const float* Wp   = (const float*)d_in[18];
    const float* bp   = (const float*)d_in[19];
    float* out = (float*)d_out;

    static h16 *wh = nullptr, *xh, *qh, *kh, *vth, *t0h, *ih;
    static cudaStream_t s1 = 0;
    static cudaEvent_t ev0 = nullptr, ev1 = nullptr, ev2 = nullptr, ev3 = nullptr;
    if (!wh) {
        cudaGetSymbolAddress((void**)&wh, g_wh);
        cudaGetSymbolAddress((void**)&xh, g_xh);
        cudaGetSymbolAddress((void**)&qh, g_qh);
        cudaGetSymbolAddress((void**)&kh, g_kh);
        cudaGetSymbolAddress((void**)&vth, g_vth);
        cudaGetSymbolAddress((void**)&t0h, g_t0h);
        cudaGetSymbolAddress((void**)&ih, g_ih);
        cudaFuncSetAttribute((const void*)tgemm<128,0,1>, cudaFuncAttributeMaxDynamicSharedMemorySize, S128);
        cudaFuncSetAttribute((const void*)tgemm<128,1,1>, cudaFuncAttributeMaxDynamicSharedMemorySize, S128);
        cudaFuncSetAttribute((const void*)tgemm<128,1,0>, cudaFuncAttributeMaxDynamicSharedMemorySize, S128);
        cudaFuncSetAttribute((const void*)qkv_gemm, cudaFuncAttributeMaxDynamicSharedMemorySize, S128);
        cudaFuncSetAttribute((const void*)flash_kernel, cudaFuncAttributeMaxDynamicSharedMemorySize, FSMEM);
        if (cudaStreamCreateWithFlags(&s1, cudaStreamNonBlocking) != cudaSuccess) s1 = 0;
        if (cudaEventCreateWithFlags(&ev0, cudaEventDisableTiming) != cudaSuccess) ev0 = nullptr;
        if (cudaEventCreateWithFlags(&ev1, cudaEventDisableTiming) != cudaSuccess) ev1 = nullptr;
        if (cudaEventCreateWithFlags(&ev2, cudaEventDisableTiming) != cudaSuccess) ev2 = nullptr;
        if (cudaEventCreateWithFlags(&ev3, cudaEventDisableTiming) != cudaSuccess) ev3 = nullptr;
    }
    const bool fork = (s1 != 0) && ev0 && ev1 && ev2 && ev3;

    const ll Z = 0;
    const ll DD = (ll)ND * ND;
    dim3 t32(32, 8);

    WJobs jobs;
    int startA = 0, total = 0;
    {
        int start = 0, j = 0;
        const float* csrc[3] = { Wq, Wk, Wv };
        for (int i = 0; i < 3; i++) {
            jobs.e[j] = { csrc[i], wh + (ll)i * DD, ND, ND, start };
            start += 1024; j++;
        }
        startA = start;
        jobs.e[j] = { Wo, wh + 3*DD, ND, ND, start };                       start += 1024; j++;
        jobs.e[j] = { Wm, wh + 4*DD, ND, NI, start };                       start += 4096; j++;
        jobs.e[j] = { Wr, wh + 4*DD + (ll)ND*NI, NI, ND, start };           start += 4096; j++;
        {
            ll o = WPL;
            const float* srcs[6] = { Wq + DD, Wk + DD, Wv + DD, Wo + DD,
                                     Wm + (ll)ND*NI, Wr + (ll)NI*ND };
            h16* dsts[6] = { wh + o, wh + o + DD, wh + o + 2*DD, wh + o + 3*DD,
                             wh + o + 4*DD, wh + o + 4*DD + (ll)ND*NI };
            int Ks[6] = { ND, ND, ND, ND, ND, NI };
            int Ns[6] = { ND, ND, ND, ND, NI, ND };
            for (int i = 0; i < 6; i++) {
                jobs.e[j] = { srcs[i], dsts[i], Ks[i], Ns[i], start };
                start += (Ks[i] / 32) * (Ns[i] / 32); j++;
            }
        }
        jobs.e[j] = { Wp, wh + (ll)NL*WPL, ND, NOUT, start };
        start += (ND / 32) * (NOUT / 32);
        total = start;
    }

    wsplit_all<<<startA, t32>>>(jobs, 0);
    if (fork) {
        cudaEventRecord(ev0, 0);
        cudaStreamWaitEvent(s1, ev0, 0);
        wsplit_all<<<total - startA, t32, 0, s1>>>(jobs, startA);
        cudaEventRecord(ev1, s1);
    } else {
        wsplit_all<<<total - startA, t32>>>(jobs, startA);
    }

    concat_kernel<<<(NBT * ND / 4 + 255) / 256, 256>>>(hs, mem);

    for (int l = 0; l < NL; l++) {
        ll o = (ll)l * WPL;
        const h16 *wqkv = wh + o;
        const h16 *woh = wh + o + 3*DD;
        const h16 *wmh = wh + o + 4*DD;
        const h16 *wrh = wh + o + 4*DD + (ll)ND*NI;

        qkv_gemm<<<dim3(8, 32, 3), 256, S128>>>(xh, wqkv,
            bq + l*ND, bk + l*ND, bv + l*ND, qh, kh, vth);

        flash_kernel<<<dim3(16, 64), 256, FSMEM>>>(qh, kh, vth, t0h);

        if (l == 0 && fork) cudaStreamWaitEvent(0, ev1, 0);

        tgemm<128,0,1><<<dim3(8, 32, 1), 256, S128>>>(t0h, woh, bo + l*ND, 1.f,
            nullptr, kh, ND, ND, ND, ND, Z,Z,Z,Z,Z,Z, 1);
        add_ln_kernel<<<NBT, 256>>>(kh, ln1g + l*ND, ln1b + l*ND);

        tgemm<128,1,1><<<dim3(32, 32, 1), 256, S128>>>(xh, wmh, bmv + l*NI, 1.f,
            nullptr, ih, ND, ND, ND, NI, Z,Z,Z,Z,Z,Z, 1);
        tgemm<128,0,1><<<dim3(8, 32, 1), 256, S128>>>(ih, wrh, br + l*ND, 1.f,
            nullptr, kh, NI, NI, NI, ND, Z,Z,Z,Z,Z,Z, 1);
        add_ln_kernel<<<NBT, 256>>>(kh, ln2g + l*ND, ln2b + l*ND);
    }

    // read_out on the side stream, concurrent with the final projection GEMM
    if (fork) {
        cudaEventRecord(ev2, 0);                     // after last add_ln (g_x final)
        cudaStreamWaitEvent(s1, ev2, 0);
        readout_kernel<<<(NB * NM * ND + 255) / 256, 256, 0, s1>>>(out);
        cudaEventRecord(ev3, s1);
    }

    tgemm<128,1,0><<<dim3(32, 7, NB), 256, S128>>>(xh + NM*ND,
        wh + (ll)NL*WPL, bp, 1.f,
        out, nullptr, ND, ND, ND, NOUT,
        (ll)NT*ND, Z, Z, Z, (ll)NS*NOUT, Z, 1);

    if (fork) cudaStreamWaitEvent(0, ev3, 0);        // join before returning
    else      readout_kernel<<<(NB * NM * ND + 255) / 256, 256>>>(out);
}